// round 3
// baseline (speedup 1.0000x reference)
#include <cuda_runtime.h>
#include <cstdint>

#define DIM    128
#define NTOK   49
#define NH     4
#define HD     32
#define NW     64
#define NBLK   4096
#define NTHR   512
#define SCALE  0.17677669529663687f
#define SLD    60

// ---- smem layout (float offsets) ----
#define SM_XP   0                       // x / attn-out, A-packed, M64 K128 : 8192
#define SM_QP   8192                    // Q A-packed per head  [4][2048]   : 8192
#define SM_KP   16384                   // K B2-packed per head [4][1792]   : 7168
#define SM_VP   23552                   // V B4-packed per head [4][1792]   : 7168
#define SM_WS   30720                   // weight dbl-buf 2x8192 | scores 4x64x60 : 16384
#define SM_RI   47104                   // 2401 int
#define SM_MSK  49505                   // 2401
#define SM_BTB  51906                   // 676
#define SM_BQ   52582                   // 384
#define SM_BP   52966                   // 128
#define SMEMF   53094                   // floats (212376 B)

// packed tf32 weights (prep kernel output)
__device__ float g_wq[49152];           // w_qkv B4-packed, nt=0..23, KT=16
__device__ float g_wp[16384];           // w_proj B4-packed, nt=0..7,  KT=16

extern __shared__ float smem[];

__device__ __forceinline__ uint32_t f2tf(float f) {
    uint32_t u;
    asm("cvt.rna.tf32.f32 %0, %1;" : "=r"(u) : "f"(f));
    return u;
}
__device__ __forceinline__ void mma8(float* c, const uint32_t* a, uint32_t b0, uint32_t b1) {
    asm("mma.sync.aligned.m16n8k8.row.col.f32.tf32.tf32.f32 "
        "{%0,%1,%2,%3},{%4,%5,%6,%7},{%8,%9},{%0,%1,%2,%3};"
        : "+f"(c[0]), "+f"(c[1]), "+f"(c[2]), "+f"(c[3])
        : "r"(a[0]), "r"(a[1]), "r"(a[2]), "r"(a[3]), "r"(b0), "r"(b1));
}
// A-pack element addr: matrix[r][c], frag regs {a0,a1,a2,a3}
__device__ __forceinline__ int ea(int r, int c, int KT) {
    return ((((r >> 4) * KT + (c >> 3)) * 4 + (c & 3)) * 8 + (r & 7)) * 4
           + ((r >> 3) & 1) + 2 * ((c >> 2) & 1);
}
// B-pack (4-slot) element addr: matrix[k][n], regs {b00,b01,b10,b11}
__device__ __forceinline__ int eb4(int k, int n, int KT) {
    return ((((n >> 4) * KT + (k >> 3)) * 4 + (k & 3)) * 8 + (n & 7)) * 4
           + ((k >> 2) & 1) + 2 * ((n >> 3) & 1);
}
// B-pack (2-slot) element addr: matrix[k][n], regs {b0,b1}
__device__ __forceinline__ int eb2(int k, int n, int KT) {
    return ((((n >> 3) * KT + (k >> 3)) * 4 + (k & 3)) * 8 + (n & 7)) * 2
           + ((k >> 2) & 1);
}
__device__ __forceinline__ void cpa16(uint32_t s, const void* g) {
    asm volatile("cp.async.cg.shared.global [%0], [%1], 16;" :: "r"(s), "l"(g));
}

// ---- prep: convert+pack weights to tf32 fragment order ----
__global__ void prep_kernel(const float* __restrict__ wq, const float* __restrict__ wp) {
    int o = blockIdx.x * blockDim.x + threadIdx.x;       // 65536
    int oo = (o < 49152) ? o : o - 49152;
    int slot = oo & 3, gid = (oo >> 2) & 7, tig = (oo >> 5) & 3, kt = (oo >> 7) & 15;
    int nt = oo >> 11;
    int k = kt * 8 + tig + 4 * (slot & 1);
    int n = nt * 16 + gid + 8 * (slot >> 1);
    if (o < 49152) g_wq[oo] = __uint_as_float(f2tf(wq[k * 384 + n]));
    else           g_wp[oo] = __uint_as_float(f2tf(wp[k * 128 + n]));
}

__global__ void __launch_bounds__(NTHR, 1)
winattn_kernel(const float* __restrict__ x,
               const float* __restrict__ mask,
               const float* __restrict__ b_qkv,
               const float* __restrict__ btab,
               const float* __restrict__ b_proj,
               const int*   __restrict__ rel_idx,
               float* __restrict__ out)
{
    const int b    = blockIdx.x;
    const int tid  = threadIdx.x;
    const int wid  = tid >> 5;
    const int lane = tid & 31;
    const int gid  = lane >> 2;
    const int tig  = lane & 3;

    uint32_t smem_u;
    asm("{ .reg .u64 t; cvta.to.shared.u64 t, %1; cvt.u32.u64 %0, t; }"
        : "=r"(smem_u) : "l"(smem));

    float* xp  = smem + SM_XP;
    float* qp  = smem + SM_QP;
    float* kp  = smem + SM_KP;
    float* vp  = smem + SM_VP;
    float* ws  = smem + SM_WS;
    int*   ri  = (int*)(smem + SM_RI);
    float* msk = smem + SM_MSK;
    float* btb = smem + SM_BTB;
    float* bqs = smem + SM_BQ;
    float* bps = smem + SM_BP;

    // prefetch weight tiles 0,1 immediately
    {
        const float* src = g_wq;
        for (int i = tid; i < 2048; i += NTHR)
            cpa16(smem_u + SM_WS * 4 + i * 16, src + i * 4);
        asm volatile("cp.async.commit_group;");
        src = g_wq + 8192;
        for (int i = tid; i < 2048; i += NTHR)
            cpa16(smem_u + (SM_WS + 8192) * 4 + i * 16, src + i * 4);
        asm volatile("cp.async.commit_group;");
    }

    // ---- Stage A: load+pack x, constants ----
    const float* xg = x + (size_t)b * (NTOK * DIM);
    for (int i = tid; i < 8192; i += NTHR) {
        int r = i >> 7, c = i & 127;
        float v = (r < NTOK) ? xg[r * DIM + c] : 0.f;
        xp[ea(r, c, 16)] = __uint_as_float(f2tf(v));
    }
    const int w = b & (NW - 1);
    const float* mg = mask + (size_t)w * (NTOK * NTOK);
    for (int i = tid; i < NTOK * NTOK; i += NTHR) { msk[i] = mg[i]; ri[i] = rel_idx[i]; }
    for (int i = tid; i < 169 * NH; i += NTHR) btb[i] = btab[i];
    if (tid < 3 * DIM) bqs[tid] = b_qkv[tid];
    if (tid < DIM)     bps[tid] = b_proj[tid];

    // ---- Stage B: QKV GEMM, double-buffered packed weights ----
    {
        const int mw = wid & 3, nw = wid >> 2;
        __syncthreads();                 // xp ready
        uint32_t ax[16][4];
        const uint4* xp4 = (const uint4*)xp;
#pragma unroll
        for (int kt = 0; kt < 16; kt++)
            *(uint4*)ax[kt] = xp4[((mw * 16 + kt) * 4 + tig) * 8 + gid];

        const int r0 = mw * 16 + gid, r1 = r0 + 8;
#pragma unroll 1
        for (int t = 0; t < 6; t++) {
            if (t == 5) asm volatile("cp.async.wait_group 0;");
            else        asm volatile("cp.async.wait_group 1;");
            __syncthreads();
            const uint4* wb = (const uint4*)(ws + (t & 1) * 8192);
            float c0[4] = {0,0,0,0}, c1[4] = {0,0,0,0};
#pragma unroll
            for (int kt = 0; kt < 16; kt++) {
                uint4 bv = wb[((nw * 16 + kt) * 4 + tig) * 8 + gid];
                mma8(c0, ax[kt], bv.x, bv.y);
                mma8(c1, ax[kt], bv.z, bv.w);
            }
            // scatter to packed Q/K/V
            const int cb = t * 64 + nw * 16;
            const float sc = (t < 2) ? SCALE : 1.f;
            float vals[8] = {c0[0], c0[1], c0[2], c0[3], c1[0], c1[1], c1[2], c1[3]};
#pragma unroll
            for (int e = 0; e < 8; e++) {
                const int col = cb + 2 * tig + (e & 1) + ((e >> 2) * 8);
                const int rr  = ((e >> 1) & 1) ? r1 : r0;
                const float val = (vals[e] + bqs[col]) * sc;
                const uint32_t tv = f2tf(val);
                if (t < 2) {
                    const int h = col >> 5, d = col & 31;
                    qp[h * 2048 + ea(rr, d, 4)] = __uint_as_float(tv);
                } else if (t < 4) {
                    const int cc = col - 128, h = cc >> 5, d = cc & 31;
                    if (rr < 56) kp[h * 1792 + eb2(d, rr, 4)] = __uint_as_float(tv);
                } else {
                    const int cc = col - 256, h = cc >> 5, d = cc & 31;
                    if (rr < 56) vp[h * 1792 + eb4(rr, d, 7)] = __uint_as_float(tv);
                }
            }
            __syncthreads();
            if (t < 4) {     // stage tile t+2 into buffer t&1
                const float* src = g_wq + (t + 2) * 8192;
                const uint32_t dst = smem_u + (SM_WS + (t & 1) * 8192) * 4;
                for (int i = tid; i < 2048; i += NTHR)
                    cpa16(dst + i * 16, src + i * 4);
                asm volatile("cp.async.commit_group;");
            }
        }
    }
    __syncthreads();

    // ---- Stage C: raw S = (q*scale) @ k^T per head ----
    {
        const int h = wid >> 2, mt = wid & 3;
        uint32_t aq[4][4];
        const uint4* qp4 = (const uint4*)qp;
#pragma unroll
        for (int kt = 0; kt < 4; kt++)
            *(uint4*)aq[kt] = qp4[h * 512 + ((mt * 4 + kt) * 4 + tig) * 8 + gid];
        const uint2* kp2 = (const uint2*)kp;
        float* S = ws + h * (64 * SLD);
        const int rr0 = mt * 16 + gid;
#pragma unroll
        for (int nt = 0; nt < 7; nt++) {
            float c[4] = {0,0,0,0};
#pragma unroll
            for (int kt = 0; kt < 4; kt++) {
                uint2 bv = kp2[h * 896 + ((nt * 4 + kt) * 4 + tig) * 8 + gid];
                mma8(c, aq[kt], bv.x, bv.y);
            }
            const int cc = nt * 8 + 2 * tig;
            *(float2*)&S[rr0 * SLD + cc]       = make_float2(c[0], c[1]);
            *(float2*)&S[(rr0 + 8) * SLD + cc] = make_float2(c[2], c[3]);
        }
    }
    __syncthreads();

    // ---- Softmax (warp per row, bias+mask folded), writes tf32 P ----
    {
        const int h = wid & 3, rb = wid >> 2;
        float* Sh = ws + h * (64 * SLD);
#pragma unroll 1
        for (int j = 0; j < 13; j++) {
            const int rr = rb + 4 * j;
            if (rr >= NTOK) break;
            float* Srow = Sh + rr * SLD;
            const int c2 = lane + 32;
            float v1 = Srow[lane] + btb[ri[rr * NTOK + lane] * NH + h] + msk[rr * NTOK + lane];
            float v2 = (c2 < NTOK)
                     ? Srow[c2] + btb[ri[rr * NTOK + c2] * NH + h] + msk[rr * NTOK + c2]
                     : -1e30f;
            float m = fmaxf(v1, v2);
#pragma unroll
            for (int o = 16; o; o >>= 1) m = fmaxf(m, __shfl_xor_sync(0xffffffffu, m, o));
            float e1 = __expf(v1 - m);
            float e2 = (c2 < NTOK) ? __expf(v2 - m) : 0.f;
            float s = e1 + e2;
#pragma unroll
            for (int o = 16; o; o >>= 1) s += __shfl_xor_sync(0xffffffffu, s, o);
            const float inv = 1.f / s;
            Srow[lane] = __uint_as_float(f2tf(e1 * inv));
            if (c2 < 56) Srow[c2] = (c2 < NTOK) ? __uint_as_float(f2tf(e2 * inv)) : 0.f;
        }
    }
    __syncthreads();

    // ---- Stage D: AO = P @ V per head -> packed xp ----
    {
        const int h = wid >> 2, mt = wid & 3;
        const int m0 = mt * 16;
        const float* S = ws + h * (64 * SLD);
        uint32_t ap[7][4];
#pragma unroll
        for (int kt = 0; kt < 7; kt++) {
            const int base = (m0 + gid) * SLD + kt * 8 + tig;
            ap[kt][0] = __float_as_uint(S[base]);
            ap[kt][1] = __float_as_uint(S[base + 8 * SLD]);
            ap[kt][2] = __float_as_uint(S[base + 4]);
            ap[kt][3] = __float_as_uint(S[base + 8 * SLD + 4]);
        }
        float c0[4] = {0,0,0,0}, c1[4] = {0,0,0,0}, c2[4] = {0,0,0,0}, c3[4] = {0,0,0,0};
        const uint4* vp4 = (const uint4*)vp;
#pragma unroll
        for (int kt = 0; kt < 7; kt++) {
            uint4 v0 = vp4[h * 448 + (kt * 4 + tig) * 8 + gid];
            uint4 v1 = vp4[h * 448 + ((7 + kt) * 4 + tig) * 8 + gid];
            mma8(c0, ap[kt], v0.x, v0.y);
            mma8(c1, ap[kt], v0.z, v0.w);
            mma8(c2, ap[kt], v1.x, v1.y);
            mma8(c3, ap[kt], v1.z, v1.w);
        }
        const int r0 = m0 + gid, r1 = r0 + 8, ch = h * HD;
        float vals[16] = {c0[0],c0[1],c0[2],c0[3], c1[0],c1[1],c1[2],c1[3],
                          c2[0],c2[1],c2[2],c2[3], c3[0],c3[1],c3[2],c3[3]};
#pragma unroll
        for (int e = 0; e < 16; e++) {
            const int col = ch + (e >> 2) * 8 + 2 * tig + (e & 1);
            const int rr  = ((e >> 1) & 1) ? r1 : r0;
            xp[ea(rr, col, 16)] = __uint_as_float(f2tf(vals[e]));
        }
    }
    __syncthreads();

    // ---- Stage E: out = AO @ w_proj + b ----
    {
        for (int i = tid; i < 4096; i += NTHR)
            cpa16(smem_u + SM_WS * 4 + i * 16, g_wp + i * 4);
        asm volatile("cp.async.commit_group;");

        const int mw = wid & 3, nw = wid >> 2;
        uint32_t ao[16][4];
        const uint4* xp4 = (const uint4*)xp;
#pragma unroll
        for (int kt = 0; kt < 16; kt++)
            *(uint4*)ao[kt] = xp4[((mw * 16 + kt) * 4 + tig) * 8 + gid];

        asm volatile("cp.async.wait_group 0;");
        __syncthreads();

        float* og = out + (size_t)b * (NTOK * DIM);
        const int r0 = mw * 16 + gid, r1 = r0 + 8;
#pragma unroll
        for (int t = 0; t < 2; t++) {
            const uint4* wb = (const uint4*)(ws + t * 8192);
            float c0[4] = {0,0,0,0}, c1[4] = {0,0,0,0};
#pragma unroll
            for (int kt = 0; kt < 16; kt++) {
                uint4 bv = wb[((nw * 16 + kt) * 4 + tig) * 8 + gid];
                mma8(c0, ao[kt], bv.x, bv.y);
                mma8(c1, ao[kt], bv.z, bv.w);
            }
            const int col = t * 64 + nw * 16 + 2 * tig;
            const float b0 = bps[col], b1 = bps[col + 1];
            const float b2 = bps[col + 8], b3 = bps[col + 9];
            if (r0 < NTOK) {
                *(float2*)&og[r0 * DIM + col]     = make_float2(c0[0] + b0, c0[1] + b1);
                *(float2*)&og[r0 * DIM + col + 8] = make_float2(c1[0] + b2, c1[1] + b3);
            }
            if (r1 < NTOK) {
                *(float2*)&og[r1 * DIM + col]     = make_float2(c0[2] + b0, c0[3] + b1);
                *(float2*)&og[r1 * DIM + col + 8] = make_float2(c1[2] + b2, c1[3] + b3);
            }
        }
    }
}

extern "C" void kernel_launch(void* const* d_in, const int* in_sizes, int n_in,
                              void* d_out, int out_size)
{
    const float* x      = (const float*)d_in[0];
    const float* mask   = (const float*)d_in[1];
    const float* w_qkv  = (const float*)d_in[2];
    const float* b_qkv  = (const float*)d_in[3];
    const float* btab   = (const float*)d_in[4];
    const float* w_proj = (const float*)d_in[5];
    const float* b_proj = (const float*)d_in[6];
    const int*   relidx = (const int*)  d_in[7];
    float* out = (float*)d_out;

    prep_kernel<<<128, 512>>>(w_qkv, w_proj);

    const int smem_bytes = SMEMF * (int)sizeof(float);
    cudaFuncSetAttribute(winattn_kernel,
                         cudaFuncAttributeMaxDynamicSharedMemorySize, smem_bytes);
    winattn_kernel<<<NBLK, NTHR, smem_bytes>>>(x, mask, b_qkv, btab,
                                               b_proj, relidx, out);
}

// round 5
// speedup vs baseline: 2.2304x; 2.2304x over previous
#include <cuda_runtime.h>
#include <cstdint>

#define NTOK   49
#define DIM    128
#define NH     4
#define NWIN   4096
#define MROWS  200704                 // 4096*49
#define SCALE  0.17677669529663687f

// ---- global scratch (static __device__, no allocation) ----
__device__ float g_wq[49152];         // w_qkv, tf32 B-frag-packed (24 n16-tiles x 2048)
__device__ float g_wp[16384];         // w_proj, tf32 B-frag-packed (8 n16-tiles)
__device__ float g_qkv[77070336];     // [200704][384]  Q(scaled)|K|V
__device__ float g_ao[25690112];      // [200704][128]  attention output

__device__ __forceinline__ uint32_t f2tf(float f) {
    uint32_t u;
    asm("cvt.rna.tf32.f32 %0, %1;" : "=r"(u) : "f"(f));
    return u;
}
__device__ __forceinline__ void mma8(float* c, const uint32_t* a, uint32_t b0, uint32_t b1) {
    asm("mma.sync.aligned.m16n8k8.row.col.f32.tf32.tf32.f32 "
        "{%0,%1,%2,%3},{%4,%5,%6,%7},{%8,%9},{%0,%1,%2,%3};"
        : "+f"(c[0]), "+f"(c[1]), "+f"(c[2]), "+f"(c[3])
        : "r"(a[0]), "r"(a[1]), "r"(a[2]), "r"(a[3]), "r"(b0), "r"(b1));
}
__device__ __forceinline__ void cpa16(uint32_t s, const void* g) {
    asm volatile("cp.async.cg.shared.global [%0], [%1], 16;" :: "r"(s), "l"(g));
}
__device__ __forceinline__ uint32_t smem_u32(const void* p) {
    uint32_t a;
    asm("{ .reg .u64 t; cvta.to.shared.u64 t, %1; cvt.u32.u64 %0, t; }" : "=r"(a) : "l"(p));
    return a;
}

// ---- prep: pack weights into tf32 B-fragment order ----
// float offset = nt*2048 + kt*128 + tig*32 + gid*4 + slot
// element = W[k = kt*8 + tig + 4*(slot&1)][n = nt*16 + gid + 8*(slot>>1)]
__global__ void prep_kernel(const float* __restrict__ wq, const float* __restrict__ wp) {
    int o = blockIdx.x * blockDim.x + threadIdx.x;        // 65536 total
    int oo = (o < 49152) ? o : o - 49152;
    int slot = oo & 3, gid = (oo >> 2) & 7, tig = (oo >> 5) & 3, kt = (oo >> 7) & 15;
    int nt = oo >> 11;
    int k = kt * 8 + tig + 4 * (slot & 1);
    int n = nt * 16 + gid + 8 * (slot >> 1);
    if (o < 49152) g_wq[oo] = __uint_as_float(f2tf(wq[k * 384 + n]));
    else           g_wp[oo] = __uint_as_float(f2tf(wp[k * 128 + n]));
}

// ============================================================
// GEMM: C[M=64-tile x N=128-tile] = A[64x128] * B + bias, K=128
// MODE 0: A=x, C=g_qkv (N=384, grid.y=3, Q tile scaled)
// MODE 1: A=g_ao, C=out (N=128, grid.y=1)
// ============================================================
#define GA_LD 132
#define GS_B  8448
#define GS_BS 24832
#define GEMM_SMEMF 24960          // 99840 B

template<int MODE>
__global__ void __launch_bounds__(256, 2)
gemm_k128(const float* __restrict__ Aext, const float* __restrict__ bias,
          float* __restrict__ Cext)
{
    extern __shared__ float sm[];
    float* As = sm;
    float* Bs = sm + GS_B;
    float* bs = sm + GS_BS;
    const int tid = threadIdx.x, wid = tid >> 5, lane = tid & 31;
    const int gid = lane >> 2, tig = lane & 3;
    const uint32_t su = smem_u32(sm);

    const float* A    = (MODE == 0) ? Aext : g_ao;
    const float* Bp   = (MODE == 0) ? (g_wq + blockIdx.y * 16384) : g_wp;
    const float* bptr = (MODE == 0) ? (bias + blockIdx.y * 128)   : bias;
    const int    NO   = (MODE == 0) ? 384 : 128;
    const int    cb   = (MODE == 0) ? blockIdx.y * 128 : 0;
    const float  sc   = (MODE == 0 && blockIdx.y == 0) ? SCALE : 1.f;

    const size_t arow0 = (size_t)blockIdx.x * 64;
    for (int i = tid; i < 2048; i += 256) {               // A 64x128
        int r = i >> 5, c4 = i & 31;
        cpa16(su + (r * GA_LD + c4 * 4) * 4, A + (arow0 + r) * DIM + c4 * 4);
    }
    for (int i = tid; i < 4096; i += 256)                 // B packed 16384 floats
        cpa16(su + (GS_B + i * 4) * 4, Bp + i * 4);
    if (tid < 128) bs[tid] = bptr[tid];
    asm volatile("cp.async.commit_group;\n\tcp.async.wait_group 0;");
    __syncthreads();

    const int mw = wid & 1, nw = wid >> 1;
    const int m0 = mw * 32;
    float c[2][4][4];
#pragma unroll
    for (int f = 0; f < 2; f++)
#pragma unroll
        for (int j = 0; j < 4; j++)
#pragma unroll
            for (int e = 0; e < 4; e++) c[f][j][e] = 0.f;

    const uint4* Bs4 = (const uint4*)Bs;
#pragma unroll
    for (int kt = 0; kt < 16; kt++) {
        uint32_t au[2][4];
#pragma unroll
        for (int f = 0; f < 2; f++) {
            const float* p = As + (m0 + f * 16 + gid) * GA_LD + kt * 8 + tig;
            au[f][0] = f2tf(p[0]);
            au[f][1] = f2tf(p[8 * GA_LD]);
            au[f][2] = f2tf(p[4]);
            au[f][3] = f2tf(p[8 * GA_LD + 4]);
        }
        uint4 bv0 = Bs4[(((nw * 2 + 0) * 16 + kt) * 4 + tig) * 8 + gid];
        uint4 bv1 = Bs4[(((nw * 2 + 1) * 16 + kt) * 4 + tig) * 8 + gid];
#pragma unroll
        for (int f = 0; f < 2; f++) {
            mma8(c[f][0], au[f], bv0.x, bv0.y);
            mma8(c[f][1], au[f], bv0.z, bv0.w);
            mma8(c[f][2], au[f], bv1.x, bv1.y);
            mma8(c[f][3], au[f], bv1.z, bv1.w);
        }
    }

    float* C = (MODE == 0) ? g_qkv : Cext;
#pragma unroll
    for (int f = 0; f < 2; f++) {
        const size_t r0 = arow0 + m0 + f * 16 + gid;
#pragma unroll
        for (int j = 0; j < 4; j++) {
            const int cl = nw * 32 + j * 8 + 2 * tig;
            const float b0 = bs[cl], b1 = bs[cl + 1];
            const int cg = cb + cl;
            *(float2*)&C[r0 * NO + cg] =
                make_float2((c[f][j][0] + b0) * sc, (c[f][j][1] + b1) * sc);
            *(float2*)&C[(r0 + 8) * NO + cg] =
                make_float2((c[f][j][2] + b0) * sc, (c[f][j][3] + b1) * sc);
        }
    }
}

// ============================================================
// Attention: per-window, register softmax, shfl P-permute
// ============================================================
#define QS_LD 388
#define AS_RI 21728
#define AS_MK 24129
#define AS_BT 26530
#define ATTN_SMEMF 27206          // 108824 B

__global__ void __launch_bounds__(256, 2)
attn_kernel(const float* __restrict__ mask, const float* __restrict__ btab,
            const int* __restrict__ relidx)
{
    extern __shared__ float sm[];
    float* qs = sm;
    int*   ri = (int*)(sm + AS_RI);
    float* mk = sm + AS_MK;
    float* bt = sm + AS_BT;
    const int tid = threadIdx.x, wid = tid >> 5, lane = tid & 31;
    const int gid = lane >> 2, tig = lane & 3;
    const uint32_t su = smem_u32(sm);

    const int wb = blockIdx.x;
    const size_t row0 = (size_t)wb * NTOK;
    for (int i = tid; i < 4704; i += 256) {               // 49x384 float4
        int r = i / 96, c4 = i % 96;
        cpa16(su + (r * QS_LD + c4 * 4) * 4, g_qkv + (row0 + r) * 384 + c4 * 4);
    }
    for (int i = tid; i < 7 * QS_LD; i += 256) qs[49 * QS_LD + i] = 0.f;   // zero rows 49..55
    const int w = wb & 63;
    for (int i = tid; i < 2401; i += 256) { mk[i] = mask[w * 2401 + i]; ri[i] = relidx[i]; }
    for (int i = tid; i < 676; i += 256) bt[i] = btab[(i % 169) * 4 + (i / 169)];  // [h][169]
    asm volatile("cp.async.commit_group;\n\tcp.async.wait_group 0;");
    __syncthreads();

    const int h = wid & 3, mt = wid >> 2;
#pragma unroll 1
    for (int sub = 0; sub < 2; sub++) {
        const int m0 = (mt * 2 + sub) * 16;
        const bool hiO = (m0 == 48);                      // rows 56..63 OOB -> zero frags

        // ---- S = Qh @ Kh^T (Q pre-scaled) ----
        uint32_t aq[4][4];
#pragma unroll
        for (int kt = 0; kt < 4; kt++) {
            const float* p = qs + (m0 + gid) * QS_LD + h * 32 + kt * 8 + tig;
            aq[kt][0] = f2tf(p[0]);
            aq[kt][2] = f2tf(p[4]);
            aq[kt][1] = hiO ? 0u : f2tf(p[8 * QS_LD]);
            aq[kt][3] = hiO ? 0u : f2tf(p[8 * QS_LD + 4]);
        }
        float s_[7][4];
#pragma unroll
        for (int nt = 0; nt < 7; nt++) {
            float cc[4] = {0.f, 0.f, 0.f, 0.f};
#pragma unroll
            for (int kt = 0; kt < 4; kt++) {
                const float* kp = qs + (nt * 8 + gid) * QS_LD + 128 + h * 32 + kt * 8 + tig;
                mma8(cc, aq[kt], f2tf(kp[0]), f2tf(kp[4]));
            }
#pragma unroll
            for (int e = 0; e < 4; e++) s_[nt][e] = cc[e];
        }

        // ---- register softmax (bias + mask folded), quad shfl reductions ----
        const int r0 = m0 + gid, r1 = r0 + 8;
        const bool v0 = r0 < NTOK, v1 = r1 < NTOK;
        float lo[7][2], hi[7][2];
        float mx0 = -1e30f, mx1 = -1e30f;
#pragma unroll
        for (int nt = 0; nt < 7; nt++)
#pragma unroll
            for (int s = 0; s < 2; s++) {
                const int cc = nt * 8 + 2 * tig + s;
                float a0 = -1e30f, a1 = -1e30f;
                if (cc < NTOK) {
                    if (v0) a0 = s_[nt][s]     + bt[h * 169 + ri[r0 * NTOK + cc]] + mk[r0 * NTOK + cc];
                    if (v1) a1 = s_[nt][2 + s] + bt[h * 169 + ri[r1 * NTOK + cc]] + mk[r1 * NTOK + cc];
                }
                lo[nt][s] = a0; hi[nt][s] = a1;
                mx0 = fmaxf(mx0, a0); mx1 = fmaxf(mx1, a1);
            }
        mx0 = fmaxf(mx0, __shfl_xor_sync(0xffffffffu, mx0, 1));
        mx0 = fmaxf(mx0, __shfl_xor_sync(0xffffffffu, mx0, 2));
        mx1 = fmaxf(mx1, __shfl_xor_sync(0xffffffffu, mx1, 1));
        mx1 = fmaxf(mx1, __shfl_xor_sync(0xffffffffu, mx1, 2));
        float s0 = 0.f, s1 = 0.f;
#pragma unroll
        for (int nt = 0; nt < 7; nt++)
#pragma unroll
            for (int s = 0; s < 2; s++) {
                float e0 = __expf(lo[nt][s] - mx0);
                float e1 = __expf(hi[nt][s] - mx1);
                lo[nt][s] = e0; hi[nt][s] = e1;
                s0 += e0; s1 += e1;
            }
        s0 += __shfl_xor_sync(0xffffffffu, s0, 1); s0 += __shfl_xor_sync(0xffffffffu, s0, 2);
        s1 += __shfl_xor_sync(0xffffffffu, s1, 1); s1 += __shfl_xor_sync(0xffffffffu, s1, 2);
        const float i0 = 1.f / s0, i1 = 1.f / s1;
#pragma unroll
        for (int nt = 0; nt < 7; nt++) {
            lo[nt][0] *= i0; lo[nt][1] *= i0;
            hi[nt][0] *= i1; hi[nt][1] *= i1;
        }

        // ---- AO = P @ Vh : permute C-frag -> A-frag via quad shfl ----
        float o[4][4];
#pragma unroll
        for (int nf = 0; nf < 4; nf++)
#pragma unroll
            for (int e = 0; e < 4; e++) o[nf][e] = 0.f;
        const int sA = tig >> 1, sB = sA + 2;
        const bool od = (tig & 1);
#pragma unroll
        for (int kt = 0; kt < 7; kt++) {
            float l0a = __shfl_sync(0xffffffffu, lo[kt][0], sA, 4);
            float l1a = __shfl_sync(0xffffffffu, lo[kt][1], sA, 4);
            float l0b = __shfl_sync(0xffffffffu, lo[kt][0], sB, 4);
            float l1b = __shfl_sync(0xffffffffu, lo[kt][1], sB, 4);
            float h0a = __shfl_sync(0xffffffffu, hi[kt][0], sA, 4);
            float h1a = __shfl_sync(0xffffffffu, hi[kt][1], sA, 4);
            float h0b = __shfl_sync(0xffffffffu, hi[kt][0], sB, 4);
            float h1b = __shfl_sync(0xffffffffu, hi[kt][1], sB, 4);
            uint32_t ap[4];
            ap[0] = f2tf(od ? l1a : l0a);
            ap[1] = f2tf(od ? h1a : h0a);
            ap[2] = f2tf(od ? l1b : l0b);
            ap[3] = f2tf(od ? h1b : h0b);
#pragma unroll
            for (int nf = 0; nf < 4; nf++) {
                const float* vp = qs + (kt * 8 + tig) * QS_LD + 256 + h * 32 + nf * 8 + gid;
                mma8(o[nf], ap, f2tf(vp[0]), f2tf(vp[4 * QS_LD]));
            }
        }
#pragma unroll
        for (int nf = 0; nf < 4; nf++) {
            const int col = h * 32 + nf * 8 + 2 * tig;
            if (v0) *(float2*)&g_ao[(row0 + r0) * DIM + col] = make_float2(o[nf][0], o[nf][1]);
            if (v1) *(float2*)&g_ao[(row0 + r1) * DIM + col] = make_float2(o[nf][2], o[nf][3]);
        }
    }
}

extern "C" void kernel_launch(void* const* d_in, const int* in_sizes, int n_in,
                              void* d_out, int out_size)
{
    const float* x      = (const float*)d_in[0];
    const float* mask   = (const float*)d_in[1];
    const float* w_qkv  = (const float*)d_in[2];
    const float* b_qkv  = (const float*)d_in[3];
    const float* btab   = (const float*)d_in[4];
    const float* w_proj = (const float*)d_in[5];
    const float* b_proj = (const float*)d_in[6];
    const int*   relidx = (const int*)  d_in[7];
    float* out = (float*)d_out;

    cudaFuncSetAttribute(gemm_k128<0>, cudaFuncAttributeMaxDynamicSharedMemorySize,
                         GEMM_SMEMF * 4);
    cudaFuncSetAttribute(gemm_k128<1>, cudaFuncAttributeMaxDynamicSharedMemorySize,
                         GEMM_SMEMF * 4);
    cudaFuncSetAttribute(attn_kernel, cudaFuncAttributeMaxDynamicSharedMemorySize,
                         ATTN_SMEMF * 4);

    prep_kernel<<<128, 512>>>(w_qkv, w_proj);
    gemm_k128<0><<<dim3(3136, 3), 256, GEMM_SMEMF * 4>>>(x, b_qkv, nullptr);
    attn_kernel<<<NWIN, 256, ATTN_SMEMF * 4>>>(mask, btab, relidx);
    gemm_k128<1><<<dim3(3136, 1), 256, GEMM_SMEMF * 4>>>(nullptr, b_proj, out);
}